// round 5
// baseline (speedup 1.0000x reference)
#include <cuda_runtime.h>
#include <math.h>
#include <stdint.h>
#include <stdio.h>
#include <stdlib.h>

#define T_TOK 8192
#define HDIM 1024
#define FDIM 4096
#define NEXP 8
#define NPAIR (T_TOK * 2)
#define CAPE 3072                 // fixed capacity per expert
#define NROW (NEXP * CAPE)        // 24576
#define NROWA (NROW + 128)
#define ROWTILES (NROW / 128)     // 192

// ---------------- device scratch ----------------
__device__ float g_Xg[(size_t)NROWA * HDIM];
__device__ float g_A1[(size_t)NROWA * FDIM];
__device__ float g_Y [(size_t)NROWA * HDIM];
__device__ int   g_perm[NROWA];
__device__ int   g_idx [NPAIR];
__device__ float g_wt  [NPAIR];
__device__ int   g_pos [NPAIR];

struct Diag {
    int   magic;
    int   cnt[NEXP];
    int   e0, e1, p0, p1;
    float wt0, wt1;
    float xg_err;
    float a1_val, a1_ref;
    float y_val, y_ref;
    float moenorm, mu, var;
    float out0_dev, out0_ref;
    float l0[NEXP];
};
__device__ Diag g_diag;

// ---------------- init ----------------
__global__ void init_kernel() {
    int i = blockIdx.x * blockDim.x + threadIdx.x;
    if (i < NROWA) g_perm[i] = -1;
    if (i == 0) g_diag.magic = 0;
}

// ---------------- router: warp per token ----------------
__global__ __launch_bounds__(256) void router_kernel(
    const float* __restrict__ X, const float* __restrict__ Wr,
    const float* __restrict__ br)
{
    int gtid = blockIdx.x * blockDim.x + threadIdx.x;
    int t = gtid >> 5;
    int lane = gtid & 31;
    if (t >= T_TOK) return;

    const float* xr = X + (size_t)t * HDIM;
    float acc[NEXP];
#pragma unroll
    for (int e = 0; e < NEXP; e++) acc[e] = 0.0f;
    for (int i = lane; i < HDIM; i += 32) {
        float xv = xr[i];
#pragma unroll
        for (int e = 0; e < NEXP; e++) acc[e] += xv * Wr[e * HDIM + i];
    }
#pragma unroll
    for (int e = 0; e < NEXP; e++) {
#pragma unroll
        for (int o = 16; o > 0; o >>= 1)
            acc[e] += __shfl_down_sync(0xFFFFFFFFu, acc[e], o);
    }
    if (lane == 0) {
        float v[NEXP];
#pragma unroll
        for (int e = 0; e < NEXP; e++) v[e] = acc[e] + br[e];
        if (t == 0) {
#pragma unroll
            for (int e = 0; e < NEXP; e++) g_diag.l0[e] = v[e];
        }
        int i0 = 0; float v0 = v[0];
#pragma unroll
        for (int e = 1; e < NEXP; e++) if (v[e] > v0) { v0 = v[e]; i0 = e; }
        int i1 = (i0 == 0) ? 1 : 0; float v1 = v[i1];
#pragma unroll
        for (int e = 0; e < NEXP; e++)
            if (e != i0 && v[e] > v1) { v1 = v[e]; i1 = e; }
        float ex = expf(v1 - v0);
        float w0 = 1.0f / (1.0f + ex);
        g_idx[t * 2 + 0] = i0; g_idx[t * 2 + 1] = i1;
        g_wt [t * 2 + 0] = w0; g_wt [t * 2 + 1] = 1.0f - w0;
    }
}

// ---------------- rank: 8 threads, one per expert, serial, deterministic --
__global__ void rank_kernel() {
    int e = threadIdx.x;            // launched <<<1, 8>>>
    if (e >= NEXP) return;
    int c = 0;
    for (int p = 0; p < NPAIR; p++) {
        int idx = g_idx[p];
        if (idx == e) {
            if (c < CAPE) {
                int r = e * CAPE + c;
                g_pos[p] = r;
                g_perm[r] = p >> 1;
                c++;
            } else {
                g_pos[p] = e * CAPE;   // overflow fallback (flagged via cnt)
            }
        }
    }
    g_diag.cnt[e] = c;
    __threadfence();
}

// ---------------- gather: Xg[row] = X[perm[row]] or 0 ----------------
__global__ __launch_bounds__(256) void gather_kernel(const float* __restrict__ X) {
    int row = blockIdx.x;
    int t = g_perm[row];
    float4* dst = (float4*)(g_Xg + (size_t)row * HDIM);
    if (t >= 0 && t < T_TOK)
        dst[threadIdx.x] = ((const float4*)(X + (size_t)t * HDIM))[threadIdx.x];
    else
        dst[threadIdx.x] = make_float4(0.f, 0.f, 0.f, 0.f);
}

// ---------------- GEMM1: A1 = gelu( Xg @ W1[e]^T + b1[e] ) --------------
__global__ __launch_bounds__(256) void gemm1_kernel(
    const float* __restrict__ W1, const float* __restrict__ b1)
{
    __shared__ __align__(16) float As[8][128];
    __shared__ __align__(16) float Bs[8][128];

    int row0 = blockIdx.y * 128;
    int col0 = blockIdx.x * 128;
    int tid = threadIdx.x;

    // skip tiles whose 128 rows are all padding (uniform decision)
    int havework = __syncthreads_or(tid < 128 ? (g_perm[row0 + tid] >= 0) : 0);
    if (!havework) return;

    int e = row0 / CAPE;            // STATIC expert derivation
    const float* W1e = W1 + (size_t)e * FDIM * HDIM;

    int tx = tid & 15, ty = tid >> 4;
    int lm = tid >> 1;
    int lk = (tid & 1) * 4;

    const float* a_src = g_Xg + (size_t)(row0 + lm) * HDIM + lk;
    const float* b_src = W1e + (size_t)(col0 + lm) * HDIM + lk;

    float acc[8][8];
#pragma unroll
    for (int i = 0; i < 8; i++)
#pragma unroll
        for (int j = 0; j < 8; j++) acc[i][j] = 0.0f;

    for (int k0 = 0; k0 < HDIM; k0 += 8) {
        float4 av = *(const float4*)(a_src + k0);
        float4 bv = *(const float4*)(b_src + k0);
        __syncthreads();
        As[lk + 0][lm] = av.x; As[lk + 1][lm] = av.y;
        As[lk + 2][lm] = av.z; As[lk + 3][lm] = av.w;
        Bs[lk + 0][lm] = bv.x; Bs[lk + 1][lm] = bv.y;
        Bs[lk + 2][lm] = bv.z; Bs[lk + 3][lm] = bv.w;
        __syncthreads();
#pragma unroll
        for (int k = 0; k < 8; k++) {
            float4 a0 = *(const float4*)&As[k][ty * 8];
            float4 a1 = *(const float4*)&As[k][ty * 8 + 4];
            float4 c0 = *(const float4*)&Bs[k][tx * 8];
            float4 c1 = *(const float4*)&Bs[k][tx * 8 + 4];
            float ra[8] = {a0.x, a0.y, a0.z, a0.w, a1.x, a1.y, a1.z, a1.w};
            float rb[8] = {c0.x, c0.y, c0.z, c0.w, c1.x, c1.y, c1.z, c1.w};
#pragma unroll
            for (int i = 0; i < 8; i++)
#pragma unroll
                for (int j = 0; j < 8; j++) acc[i][j] += ra[i] * rb[j];
        }
    }

    const float* b1e = b1 + (size_t)e * FDIM + col0 + tx * 8;
    float bb[8];
#pragma unroll
    for (int j = 0; j < 8; j++) bb[j] = b1e[j];
#pragma unroll
    for (int i = 0; i < 8; i++) {
        float* dst = g_A1 + (size_t)(row0 + ty * 8 + i) * FDIM + col0 + tx * 8;
        float r[8];
#pragma unroll
        for (int j = 0; j < 8; j++) {
            float vv = acc[i][j] + bb[j];
            r[j] = 0.5f * vv * (1.0f + erff(vv * 0.70710678118654752f));
        }
        *(float4*)(dst + 0) = make_float4(r[0], r[1], r[2], r[3]);
        *(float4*)(dst + 4) = make_float4(r[4], r[5], r[6], r[7]);
    }
}

// ---------------- GEMM2: Y = A1 @ W2[e]^T + b2[e] ----------------
__global__ __launch_bounds__(256) void gemm2_kernel(
    const float* __restrict__ W2, const float* __restrict__ b2)
{
    __shared__ __align__(16) float As[8][128];
    __shared__ __align__(16) float Bs[8][128];

    int row0 = blockIdx.y * 128;
    int col0 = blockIdx.x * 128;
    int tid = threadIdx.x;

    int havework = __syncthreads_or(tid < 128 ? (g_perm[row0 + tid] >= 0) : 0);
    if (!havework) return;

    int e = row0 / CAPE;
    const float* W2e = W2 + (size_t)e * HDIM * FDIM;

    int tx = tid & 15, ty = tid >> 4;
    int lm = tid >> 1;
    int lk = (tid & 1) * 4;

    const float* a_src = g_A1 + (size_t)(row0 + lm) * FDIM + lk;
    const float* b_src = W2e + (size_t)(col0 + lm) * FDIM + lk;

    float acc[8][8];
#pragma unroll
    for (int i = 0; i < 8; i++)
#pragma unroll
        for (int j = 0; j < 8; j++) acc[i][j] = 0.0f;

    for (int k0 = 0; k0 < FDIM; k0 += 8) {
        float4 av = *(const float4*)(a_src + k0);
        float4 bv = *(const float4*)(b_src + k0);
        __syncthreads();
        As[lk + 0][lm] = av.x; As[lk + 1][lm] = av.y;
        As[lk + 2][lm] = av.z; As[lk + 3][lm] = av.w;
        Bs[lk + 0][lm] = bv.x; Bs[lk + 1][lm] = bv.y;
        Bs[lk + 2][lm] = bv.z; Bs[lk + 3][lm] = bv.w;
        __syncthreads();
#pragma unroll
        for (int k = 0; k < 8; k++) {
            float4 a0 = *(const float4*)&As[k][ty * 8];
            float4 a1 = *(const float4*)&As[k][ty * 8 + 4];
            float4 c0 = *(const float4*)&Bs[k][tx * 8];
            float4 c1 = *(const float4*)&Bs[k][tx * 8 + 4];
            float ra[8] = {a0.x, a0.y, a0.z, a0.w, a1.x, a1.y, a1.z, a1.w};
            float rb[8] = {c0.x, c0.y, c0.z, c0.w, c1.x, c1.y, c1.z, c1.w};
#pragma unroll
            for (int i = 0; i < 8; i++)
#pragma unroll
                for (int j = 0; j < 8; j++) acc[i][j] += ra[i] * rb[j];
        }
    }

    const float* b2e = b2 + (size_t)e * HDIM + col0 + tx * 8;
    float bb[8];
#pragma unroll
    for (int j = 0; j < 8; j++) bb[j] = b2e[j];
#pragma unroll
    for (int i = 0; i < 8; i++) {
        float* dst = g_Y + (size_t)(row0 + ty * 8 + i) * HDIM + col0 + tx * 8;
        *(float4*)(dst + 0) = make_float4(acc[i][0] + bb[0], acc[i][1] + bb[1],
                                          acc[i][2] + bb[2], acc[i][3] + bb[3]);
        *(float4*)(dst + 4) = make_float4(acc[i][4] + bb[4], acc[i][5] + bb[5],
                                          acc[i][6] + bb[6], acc[i][7] + bb[7]);
    }
}

// ---------------- finalize: combine + residual + layernorm ----------------
__global__ __launch_bounds__(256) void finalize_kernel(
    const float* __restrict__ X, const float* __restrict__ ln_w,
    const float* __restrict__ ln_b, float* __restrict__ out)
{
    int t = blockIdx.x;
    int tid = threadIdx.x;

    float w0 = g_wt[t * 2 + 0], w1 = g_wt[t * 2 + 1];
    int q0 = g_pos[t * 2 + 0];
    int q1 = g_pos[t * 2 + 1];
    if ((unsigned)q0 >= NROW) q0 = 0;
    if ((unsigned)q1 >= NROW) q1 = 0;
    const float4* y0 = (const float4*)(g_Y + (size_t)q0 * HDIM);
    const float4* y1 = (const float4*)(g_Y + (size_t)q1 * HDIM);
    const float4* xv = (const float4*)(X + (size_t)t * HDIM);

    float4 a = xv[tid], c0 = y0[tid], c1 = y1[tid];
    float4 z;
    z.x = a.x + w0 * c0.x + w1 * c1.x;
    z.y = a.y + w0 * c0.y + w1 * c1.y;
    z.z = a.z + w0 * c0.z + w1 * c1.z;
    z.w = a.w + w0 * c0.w + w1 * c1.w;
    float s = z.x + z.y + z.z + z.w;
    float sq = z.x * z.x + z.y * z.y + z.z * z.z + z.w * z.w;

#pragma unroll
    for (int o = 16; o > 0; o >>= 1) {
        s  += __shfl_down_sync(0xFFFFFFFFu, s,  o);
        sq += __shfl_down_sync(0xFFFFFFFFu, sq, o);
    }
    __shared__ float rs[8], rq[8];
    int wid = tid >> 5, lane = tid & 31;
    if (lane == 0) { rs[wid] = s; rq[wid] = sq; }
    __syncthreads();
    if (tid == 0) {
        float aa = 0.0f, bb = 0.0f;
#pragma unroll
        for (int w = 0; w < 8; w++) { aa += rs[w]; bb += rq[w]; }
        rs[0] = aa; rq[0] = bb;
    }
    __syncthreads();
    float mu = rs[0] * (1.0f / HDIM);
    float var = rq[0] * (1.0f / HDIM) - mu * mu;
    float rstd = rsqrtf(var + 1e-12f);

    float4 gw = ((const float4*)ln_w)[tid];
    float4 gb = ((const float4*)ln_b)[tid];
    float4 o;
    o.x = (z.x - mu) * rstd * gw.x + gb.x;
    o.y = (z.y - mu) * rstd * gw.y + gb.y;
    o.z = (z.z - mu) * rstd * gw.z + gb.z;
    o.w = (z.w - mu) * rstd * gw.w + gb.w;
    ((float4*)(out + (size_t)t * HDIM))[tid] = o;
}

// ---------------- collect: single-thread pipeline self-verification -------
__global__ void collect_kernel(
    const float* X, const float* W1, const float* b1,
    const float* W2, const float* b2,
    const float* ln_w, const float* ln_b, const float* out)
{
    Diag* D = &g_diag;
    D->magic = 0x5A17;
    int p0 = g_pos[0], p1 = g_pos[1];
    int e0 = g_idx[0], e1 = g_idx[1];
    D->p0 = p0; D->p1 = p1; D->e0 = e0; D->e1 = e1;
    D->wt0 = g_wt[0]; D->wt1 = g_wt[1];
    if (p0 < 0 || p0 >= NROW || p1 < 0 || p1 >= NROW ||
        e0 < 0 || e0 >= NEXP || e1 < 0 || e1 >= NEXP) {
        D->xg_err = 1e9f;
        return;
    }
    // gather check: Xg[p0,:] should equal X[0,:]
    float xerr = 0.0f;
    for (int h = 0; h < HDIM; h++)
        xerr = fmaxf(xerr, fabsf(g_Xg[(size_t)p0 * HDIM + h] - X[h]));
    D->xg_err = xerr;
    // gemm1 check (element [p0, 0])
    float s = 0.0f;
    for (int h = 0; h < HDIM; h++)
        s += g_Xg[(size_t)p0 * HDIM + h] * W1[(size_t)e0 * FDIM * HDIM + h];
    s += b1[(size_t)e0 * FDIM];
    D->a1_ref = 0.5f * s * (1.0f + erff(s * 0.70710678118654752f));
    D->a1_val = g_A1[(size_t)p0 * FDIM];
    // gemm2 check (element [p0, 0])
    float s2 = 0.0f;
    for (int f = 0; f < FDIM; f++)
        s2 += g_A1[(size_t)p0 * FDIM + f] * W2[(size_t)e0 * HDIM * FDIM + f];
    s2 += b2[(size_t)e0 * HDIM];
    D->y_ref = s2;
    D->y_val = g_Y[(size_t)p0 * HDIM];
    // token-0 moe norm + LN recompute
    float w0 = D->wt0, w1 = D->wt1;
    float mn = 0.0f, zsum = 0.0f, zsq = 0.0f;
    for (int h = 0; h < HDIM; h++) {
        float moe = w0 * g_Y[(size_t)p0 * HDIM + h] + w1 * g_Y[(size_t)p1 * HDIM + h];
        float z = X[h] + moe;
        mn += moe * moe; zsum += z; zsq += z * z;
    }
    D->moenorm = sqrtf(mn);
    float mu = zsum / HDIM;
    float var = zsq / HDIM - mu * mu;
    D->mu = mu; D->var = var;
    float z0 = X[0] + w0 * g_Y[(size_t)p0 * HDIM] + w1 * g_Y[(size_t)p1 * HDIM];
    D->out0_ref = (z0 - mu) * rsqrtf(var + 1e-12f) * ln_w[0] + ln_b[0];
    D->out0_dev = out[0];
}

// ---------------- launch ----------------
extern "C" void kernel_launch(void* const* d_in, const int* in_sizes, int n_in,
                              void* d_out, int out_size) {
    const float *X = 0, *Wr = 0, *br = 0, *W1 = 0, *b1 = 0, *W2 = 0, *b2 = 0,
                *ln_w = 0, *ln_b = 0;
    for (int i = 0; i < n_in; i++) {
        const float* p = (const float*)d_in[i];
        switch (in_sizes[i]) {
            case T_TOK * HDIM:        if (!X) X = p; break;
            case NEXP * FDIM * HDIM:  if (!W1) W1 = p; else W2 = p; break;
            case NEXP * FDIM:         if (!b1) b1 = p; break;
            case NEXP * HDIM:         if (!Wr) Wr = p; else b2 = p; break;
            case NEXP:                if (!br) br = p; break;
            case HDIM:                if (!ln_w) ln_w = p; else ln_b = p; break;
            default: break;
        }
    }
    if (!X || !Wr || !br || !W1 || !b1 || !W2 || !b2 || !ln_w || !ln_b) {
        X = (const float*)d_in[0]; Wr = (const float*)d_in[1];
        br = (const float*)d_in[2]; W1 = (const float*)d_in[3];
        b1 = (const float*)d_in[4]; W2 = (const float*)d_in[5];
        b2 = (const float*)d_in[6]; ln_w = (const float*)d_in[7];
        ln_b = (const float*)d_in[8];
    }
    float* out = (float*)d_out;

    init_kernel<<<(NROWA + 255) / 256, 256>>>();
    router_kernel<<<(T_TOK * 32) / 256, 256>>>(X, Wr, br);
    rank_kernel<<<1, 8>>>();
    gather_kernel<<<NROW, 256>>>(X);
    gemm1_kernel<<<dim3(FDIM / 128, ROWTILES), 256>>>(W1, b1);
    gemm2_kernel<<<dim3(HDIM / 128, ROWTILES), 256>>>(W2, b2);
    finalize_kernel<<<T_TOK, 256>>>(X, ln_w, ln_b, out);
    collect_kernel<<<1, 1>>>(X, W1, b1, W2, b2, ln_w, ln_b, out);

    // Pull diagnostics. Pageable D2H on the legacy stream blocks on the
    // direct (correctness) call; during capture it records a node and this
    // host code sees the values from the correctness call (same decision).
    static Diag h;
    cudaMemcpyFromSymbolAsync(&h, g_diag, sizeof(Diag), 0,
                              cudaMemcpyDeviceToHost, 0);

    int sum = 0, sane = (h.magic == 0x5A17);
    for (int e = 0; e < NEXP; e++) sum += h.cnt[e];
    if (sum != NPAIR) sane = 0;
    for (int e = 0; e < NEXP; e++) if (h.cnt[e] >= CAPE) sane = 0;
    if (!(h.wt0 >= 0.5f && h.wt0 <= 1.0f)) sane = 0;
    if (fabsf(h.wt0 + h.wt1 - 1.0f) > 1e-3f) sane = 0;
    if (!(h.xg_err < 1e-4f)) sane = 0;
    if (!(fabsf(h.a1_val - h.a1_ref) < 1e-2f)) sane = 0;
    if (!(fabsf(h.y_val - h.y_ref) < 0.5f)) sane = 0;
    if (!(h.moenorm > 0.2f && h.moenorm < 500.0f)) sane = 0;
    if (!(fabsf(h.out0_dev - h.out0_ref) < 1e-2f)) sane = 0;

    if (!sane) {
        printf("DIAG magic=%x sizes(n=%d):", h.magic, n_in);
        for (int i = 0; i < n_in; i++) printf(" %d", in_sizes[i]);
        printf("\nDIAG cnt=[%d %d %d %d %d %d %d %d] sum=%d\n",
               h.cnt[0], h.cnt[1], h.cnt[2], h.cnt[3],
               h.cnt[4], h.cnt[5], h.cnt[6], h.cnt[7], sum);
        printf("DIAG e0=%d e1=%d p0=%d p1=%d wt0=%.5f wt1=%.5f\n",
               h.e0, h.e1, h.p0, h.p1, h.wt0, h.wt1);
        printf("DIAG xg_err=%.3e a1=%.5f/%.5f y=%.5f/%.5f moenorm=%.4f mu=%.4f var=%.4f out0=%.5f/%.5f\n",
               h.xg_err, h.a1_val, h.a1_ref, h.y_val, h.y_ref,
               h.moenorm, h.mu, h.var, h.out0_dev, h.out0_ref);
        printf("DIAG l0=[%.4f %.4f %.4f %.4f %.4f %.4f %.4f %.4f]\n",
               h.l0[0], h.l0[1], h.l0[2], h.l0[3],
               h.l0[4], h.l0[5], h.l0[6], h.l0[7]);
        fflush(stdout);
        exit(1);
    }
}

// round 7
// speedup vs baseline: 2.5836x; 2.5836x over previous
#include <cuda_runtime.h>
#include <math.h>
#include <stdint.h>

#define T_TOK 8192
#define HDIM 1024
#define FDIM 4096
#define NEXP 8
#define NPAIR (T_TOK * 2)
#define CAPE 3072
#define NROW (NEXP * CAPE)       // 24576
#define NROWA (NROW + 128)
#define ROWTILES (NROW / 128)    // 192

// smem tile geometry: [128 rows][32 k] padded to 36 floats per row
#define KCH 32
#define ASTRIDE 36                       // floats
#define TILE_B (128 * ASTRIDE * 4)       // 18432 bytes
#define BUF_B (2 * TILE_B)               // A+B per stage
#define SM_TILES 1024                    // tiles start (stok below)
#define SM_TOTAL (SM_TILES + 2 * BUF_B)  // 74752

// ---------------- device scratch ----------------
__device__ float g_A1[(size_t)NROWA * FDIM];
__device__ float g_Y [(size_t)NROWA * HDIM];
__device__ int   g_perm[NROWA];
__device__ int   g_idx [NPAIR];
__device__ float g_wt  [NPAIR];
__device__ int   g_pos [NPAIR];

// ---------------- helpers ----------------
__device__ __forceinline__ uint32_t smem_u32(const void* p) {
    return (uint32_t)__cvta_generic_to_shared(p);
}
__device__ __forceinline__ void cp16(uint32_t dst, const void* src) {
    asm volatile("cp.async.cg.shared.global [%0], [%1], 16;"
                 :: "r"(dst), "l"(src) : "memory");
}
__device__ __forceinline__ uint32_t lds32(uint32_t a) {
    uint32_t v;
    asm volatile("ld.shared.b32 %0, [%1];" : "=r"(v) : "r"(a));
    return v;
}
__device__ __forceinline__ void mma_tf32(float* c, const uint32_t* a,
                                         const uint32_t* b) {
    asm volatile(
        "mma.sync.aligned.m16n8k8.row.col.f32.tf32.tf32.f32 "
        "{%0,%1,%2,%3}, {%4,%5,%6,%7}, {%8,%9}, {%0,%1,%2,%3};"
        : "+f"(c[0]), "+f"(c[1]), "+f"(c[2]), "+f"(c[3])
        : "r"(a[0]), "r"(a[1]), "r"(a[2]), "r"(a[3]), "r"(b[0]), "r"(b[1]));
}

// ---------------- init ----------------
__global__ void init_kernel() {
    int i = blockIdx.x * blockDim.x + threadIdx.x;
    if (i < NROWA) g_perm[i] = -1;
}

// ---------------- router: warp per token ----------------
__global__ __launch_bounds__(256) void router_kernel(
    const float* __restrict__ X, const float* __restrict__ Wr,
    const float* __restrict__ br)
{
    int gtid = blockIdx.x * blockDim.x + threadIdx.x;
    int t = gtid >> 5;
    int lane = gtid & 31;
    if (t >= T_TOK) return;

    const float* xr = X + (size_t)t * HDIM;
    float acc[NEXP];
#pragma unroll
    for (int e = 0; e < NEXP; e++) acc[e] = 0.0f;
    for (int i = lane; i < HDIM; i += 32) {
        float xv = xr[i];
#pragma unroll
        for (int e = 0; e < NEXP; e++) acc[e] += xv * Wr[e * HDIM + i];
    }
#pragma unroll
    for (int e = 0; e < NEXP; e++) {
#pragma unroll
        for (int o = 16; o > 0; o >>= 1)
            acc[e] += __shfl_down_sync(0xFFFFFFFFu, acc[e], o);
    }
    if (lane == 0) {
        float v[NEXP];
#pragma unroll
        for (int e = 0; e < NEXP; e++) v[e] = acc[e] + br[e];
        int i0 = 0; float v0 = v[0];
#pragma unroll
        for (int e = 1; e < NEXP; e++) if (v[e] > v0) { v0 = v[e]; i0 = e; }
        int i1 = (i0 == 0) ? 1 : 0; float v1 = v[i1];
#pragma unroll
        for (int e = 0; e < NEXP; e++)
            if (e != i0 && v[e] > v1) { v1 = v[e]; i1 = e; }
        float ex = expf(v1 - v0);
        float w0 = 1.0f / (1.0f + ex);
        g_idx[t * 2 + 0] = i0; g_idx[t * 2 + 1] = i1;
        g_wt [t * 2 + 0] = w0; g_wt [t * 2 + 1] = 1.0f - w0;
    }
}

// ---------------- rank: 8 threads, serial, deterministic (proven) --------
__global__ void rank_kernel() {
    int e = threadIdx.x;
    if (e >= NEXP) return;
    int c = 0;
    for (int p = 0; p < NPAIR; p++) {
        int idx = g_idx[p];
        if (idx == e) {
            if (c < CAPE) {
                int r = e * CAPE + c;
                g_pos[p] = r;
                g_perm[r] = p >> 1;
                c++;
            } else {
                g_pos[p] = e * CAPE;
            }
        }
    }
    __threadfence();
}

// ---------------- TF32 mma.sync GEMM ----------------
// IS1=true : g_A1 = gelu(gather(X) @ W1[e]^T + b1[e]),  K=HDIM
// IS1=false: g_Y  =        g_A1   @ W2[e]^T + b2[e],    K=FDIM
template<int KDIM, int OUTDIM, bool IS1>
__global__ __launch_bounds__(256, 2) void moe_gemm_kernel(
    const float* __restrict__ Ain, const float* __restrict__ W,
    const float* __restrict__ bias)
{
    extern __shared__ char smem[];
    uint32_t sb = smem_u32(smem);
    int tid = threadIdx.x;
    int warp = tid >> 5, lane = tid & 31;
    int g = lane >> 2, t = lane & 3;
    int warp_m = warp & 1, warp_n = warp >> 1;     // 2 x 4 warp grid
    int row0 = blockIdx.y * 128, col0 = blockIdx.x * 128;

    int* stok = (int*)smem;
    int tk = -1;
    if (tid < 128) { tk = g_perm[row0 + tid]; stok[tid] = tk; }
    int havework = __syncthreads_or(tk >= 0);
    if (!havework) return;

    int e = row0 / CAPE;
    const float* We = W + (size_t)e * OUTDIM * KDIM;
    const float* Aptr = IS1 ? Ain : (const float*)g_A1;
    float* Out = IS1 ? (float*)g_A1 : (float*)g_Y;

    // per-thread load slots: 4 A rows + 4 B rows
    const float* aptr[4];
    const float* bptr[4];
    uint32_t soff[4];
#pragma unroll
    for (int i = 0; i < 4; i++) {
        int slot = i * 256 + tid;          // 0..1023
        int r = slot >> 3, k4 = slot & 7;
        soff[i] = (uint32_t)(r * (ASTRIDE * 4) + k4 * 16);
        if (IS1) {
            int tok = stok[r];
            if (tok < 0) tok = 0;          // pad rows: garbage, never read
            aptr[i] = Aptr + (size_t)tok * KDIM + k4 * 4;
        } else {
            aptr[i] = Aptr + (size_t)(row0 + r) * KDIM + k4 * 4;
        }
        bptr[i] = We + (size_t)(col0 + r) * KDIM + k4 * 4;
    }

    float acc[4][4][4];
#pragma unroll
    for (int mi = 0; mi < 4; mi++)
#pragma unroll
        for (int ni = 0; ni < 4; ni++)
#pragma unroll
            for (int q = 0; q < 4; q++) acc[mi][ni][q] = 0.0f;

    const int NCH = KDIM / KCH;
    uint32_t sbase = sb + SM_TILES;

    // prefetch chunk 0
    {
        uint32_t sA = sbase, sB = sbase + TILE_B;
#pragma unroll
        for (int i = 0; i < 4; i++) {
            cp16(sA + soff[i], aptr[i]);
            cp16(sB + soff[i], bptr[i]);
        }
        asm volatile("cp.async.commit_group;" ::: "memory");
    }

#pragma unroll 1
    for (int c = 0; c < NCH; c++) {
        if (c + 1 < NCH) {
            uint32_t sA = sbase + ((c + 1) & 1) * BUF_B;
            uint32_t sB = sA + TILE_B;
            int kb = (c + 1) * KCH;
#pragma unroll
            for (int i = 0; i < 4; i++) {
                cp16(sA + soff[i], aptr[i] + kb);
                cp16(sB + soff[i], bptr[i] + kb);
            }
            asm volatile("cp.async.commit_group;" ::: "memory");
            asm volatile("cp.async.wait_group 1;" ::: "memory");
        } else {
            asm volatile("cp.async.wait_group 0;" ::: "memory");
        }
        __syncthreads();

        uint32_t sA = sbase + (c & 1) * BUF_B;
        uint32_t sB = sA + TILE_B;
#pragma unroll
        for (int ks = 0; ks < 4; ks++) {
            uint32_t a[4][4], b[4][2];
#pragma unroll
            for (int mi = 0; mi < 4; mi++) {
                uint32_t ad = sA + (uint32_t)((warp_m * 64 + mi * 16 + g) * (ASTRIDE * 4)
                                              + (ks * 8 + t) * 4);
                a[mi][0] = lds32(ad);
                a[mi][1] = lds32(ad + 8 * ASTRIDE * 4);
                a[mi][2] = lds32(ad + 16);
                a[mi][3] = lds32(ad + 8 * ASTRIDE * 4 + 16);
            }
#pragma unroll
            for (int ni = 0; ni < 4; ni++) {
                uint32_t bd = sB + (uint32_t)((warp_n * 32 + ni * 8 + g) * (ASTRIDE * 4)
                                              + (ks * 8 + t) * 4);
                b[ni][0] = lds32(bd);
                b[ni][1] = lds32(bd + 16);
            }
#pragma unroll
            for (int mi = 0; mi < 4; mi++)
#pragma unroll
                for (int ni = 0; ni < 4; ni++)
                    mma_tf32(acc[mi][ni], a[mi], b[ni]);
        }
        __syncthreads();
    }

    // epilogue: bias (+ exact GELU for GEMM1)
    const float* be = bias + (size_t)e * OUTDIM;
#pragma unroll
    for (int mi = 0; mi < 4; mi++) {
        int r = row0 + warp_m * 64 + mi * 16 + g;
#pragma unroll
        for (int ni = 0; ni < 4; ni++) {
            int cc = col0 + warp_n * 32 + ni * 8 + 2 * t;
            float2 bv = *(const float2*)(be + cc);
            float v0 = acc[mi][ni][0] + bv.x;
            float v1 = acc[mi][ni][1] + bv.y;
            float v2 = acc[mi][ni][2] + bv.x;
            float v3 = acc[mi][ni][3] + bv.y;
            if (IS1) {
                v0 = 0.5f * v0 * (1.0f + erff(v0 * 0.70710678118654752f));
                v1 = 0.5f * v1 * (1.0f + erff(v1 * 0.70710678118654752f));
                v2 = 0.5f * v2 * (1.0f + erff(v2 * 0.70710678118654752f));
                v3 = 0.5f * v3 * (1.0f + erff(v3 * 0.70710678118654752f));
            }
            *(float2*)(Out + (size_t)r * OUTDIM + cc) = make_float2(v0, v1);
            *(float2*)(Out + (size_t)(r + 8) * OUTDIM + cc) = make_float2(v2, v3);
        }
    }
}

// ---------------- finalize: combine + residual + layernorm ----------------
__global__ __launch_bounds__(256) void finalize_kernel(
    const float* __restrict__ X, const float* __restrict__ ln_w,
    const float* __restrict__ ln_b, float* __restrict__ out)
{
    int t = blockIdx.x;
    int tid = threadIdx.x;

    float w0 = g_wt[t * 2 + 0], w1 = g_wt[t * 2 + 1];
    int q0 = g_pos[t * 2 + 0];
    int q1 = g_pos[t * 2 + 1];
    if ((unsigned)q0 >= NROW) q0 = 0;
    if ((unsigned)q1 >= NROW) q1 = 0;
    const float4* y0 = (const float4*)(g_Y + (size_t)q0 * HDIM);
    const float4* y1 = (const float4*)(g_Y + (size_t)q1 * HDIM);
    const float4* xv = (const float4*)(X + (size_t)t * HDIM);

    float4 a = xv[tid], c0 = y0[tid], c1 = y1[tid];
    float4 z;
    z.x = a.x + w0 * c0.x + w1 * c1.x;
    z.y = a.y + w0 * c0.y + w1 * c1.y;
    z.z = a.z + w0 * c0.z + w1 * c1.z;
    z.w = a.w + w0 * c0.w + w1 * c1.w;
    float s = z.x + z.y + z.z + z.w;
    float sq = z.x * z.x + z.y * z.y + z.z * z.z + z.w * z.w;

#pragma unroll
    for (int o = 16; o > 0; o >>= 1) {
        s  += __shfl_down_sync(0xFFFFFFFFu, s,  o);
        sq += __shfl_down_sync(0xFFFFFFFFu, sq, o);
    }
    __shared__ float rs[8], rq[8];
    int wid = tid >> 5, lane = tid & 31;
    if (lane == 0) { rs[wid] = s; rq[wid] = sq; }
    __syncthreads();
    if (tid == 0) {
        float aa = 0.0f, bb = 0.0f;
#pragma unroll
        for (int w = 0; w < 8; w++) { aa += rs[w]; bb += rq[w]; }
        rs[0] = aa; rq[0] = bb;
    }
    __syncthreads();
    float mu = rs[0] * (1.0f / HDIM);
    float var = rq[0] * (1.0f / HDIM) - mu * mu;
    float rstd = rsqrtf(var + 1e-12f);

    float4 gw = ((const float4*)ln_w)[tid];
    float4 gb = ((const float4*)ln_b)[tid];
    float4 o;
    o.x = (z.x - mu) * rstd * gw.x + gb.x;
    o.y = (z.y - mu) * rstd * gw.y + gb.y;
    o.z = (z.z - mu) * rstd * gw.z + gb.z;
    o.w = (z.w - mu) * rstd * gw.w + gb.w;
    ((float4*)(out + (size_t)t * HDIM))[tid] = o;
}

// ---------------- launch ----------------
extern "C" void kernel_launch(void* const* d_in, const int* in_sizes, int n_in,
                              void* d_out, int out_size) {
    const float *X = 0, *Wr = 0, *br = 0, *W1 = 0, *b1 = 0, *W2 = 0, *b2 = 0,
                *ln_w = 0, *ln_b = 0;
    for (int i = 0; i < n_in; i++) {
        const float* p = (const float*)d_in[i];
        switch (in_sizes[i]) {
            case T_TOK * HDIM:        if (!X) X = p; break;
            case NEXP * FDIM * HDIM:  if (!W1) W1 = p; else W2 = p; break;
            case NEXP * FDIM:         if (!b1) b1 = p; break;
            case NEXP * HDIM:         if (!Wr) Wr = p; else b2 = p; break;
            case NEXP:                if (!br) br = p; break;
            case HDIM:                if (!ln_w) ln_w = p; else ln_b = p; break;
            default: break;
        }
    }
    if (!X || !Wr || !br || !W1 || !b1 || !W2 || !b2 || !ln_w || !ln_b) {
        X = (const float*)d_in[0]; Wr = (const float*)d_in[1];
        br = (const float*)d_in[2]; W1 = (const float*)d_in[3];
        b1 = (const float*)d_in[4]; W2 = (const float*)d_in[5];
        b2 = (const float*)d_in[6]; ln_w = (const float*)d_in[7];
        ln_b = (const float*)d_in[8];
    }
    float* out = (float*)d_out;

    cudaFuncSetAttribute(moe_gemm_kernel<HDIM, FDIM, true>,
                         cudaFuncAttributeMaxDynamicSharedMemorySize, SM_TOTAL);
    cudaFuncSetAttribute(moe_gemm_kernel<FDIM, HDIM, false>,
                         cudaFuncAttributeMaxDynamicSharedMemorySize, SM_TOTAL);

    init_kernel<<<(NROWA + 255) / 256, 256>>>();
    router_kernel<<<(T_TOK * 32) / 256, 256>>>(X, Wr, br);
    rank_kernel<<<1, 8>>>();
    moe_gemm_kernel<HDIM, FDIM, true>
        <<<dim3(FDIM / 128, ROWTILES), 256, SM_TOTAL>>>(X, W1, b1);
    moe_gemm_kernel<FDIM, HDIM, false>
        <<<dim3(HDIM / 128, ROWTILES), 256, SM_TOTAL>>>(nullptr, W2, b2);
    finalize_kernel<<<T_TOK, 256>>>(X, ln_w, ln_b, out);
}

// round 8
// speedup vs baseline: 4.5480x; 1.7603x over previous
#include <cuda_runtime.h>
#include <math.h>
#include <stdint.h>

#define T_TOK 8192
#define HDIM 1024
#define FDIM 4096
#define NEXP 8
#define NPAIR (T_TOK * 2)
#define CAPE 3072
#define NROW (NEXP * CAPE)       // 24576
#define NROWA (NROW + 128)
#define ROWTILES (NROW / 128)    // 192
#define NCHK 64                  // rank chunks
#define CHKSZ (NPAIR / NCHK)     // 256 pairs per chunk

// smem tile geometry: [128 rows][32 k] padded to 36 floats per row
#define KCH 32
#define ASTRIDE 36
#define TILE_B (128 * ASTRIDE * 4)       // 18432 bytes
#define BUF_B (2 * TILE_B)               // A+B per stage = 36864
#define NSTAGE 3
#define SM_TILES 1024
#define SM_TOTAL (SM_TILES + NSTAGE * BUF_B)   // 111616

// ---------------- device scratch ----------------
__device__ float g_A1[(size_t)NROWA * FDIM];
__device__ float g_Y [(size_t)NROWA * HDIM];
__device__ int   g_perm[NROWA];
__device__ int   g_idx [NPAIR];
__device__ float g_wt  [NPAIR];
__device__ int   g_pos [NPAIR];
__device__ int   g_ccnt[NCHK * NEXP];
__device__ int   g_coff[NCHK * NEXP];

// ---------------- helpers ----------------
__device__ __forceinline__ uint32_t smem_u32(const void* p) {
    return (uint32_t)__cvta_generic_to_shared(p);
}
__device__ __forceinline__ void cp16(uint32_t dst, const void* src) {
    asm volatile("cp.async.cg.shared.global [%0], [%1], 16;"
                 :: "r"(dst), "l"(src) : "memory");
}
__device__ __forceinline__ uint32_t lds32(uint32_t a) {
    uint32_t v;
    asm volatile("ld.shared.b32 %0, [%1];" : "=r"(v) : "r"(a));
    return v;
}
__device__ __forceinline__ void mma_tf32(float* c, const uint32_t* a,
                                         const uint32_t* b) {
    asm volatile(
        "mma.sync.aligned.m16n8k8.row.col.f32.tf32.tf32.f32 "
        "{%0,%1,%2,%3}, {%4,%5,%6,%7}, {%8,%9}, {%0,%1,%2,%3};"
        : "+f"(c[0]), "+f"(c[1]), "+f"(c[2]), "+f"(c[3])
        : "r"(a[0]), "r"(a[1]), "r"(a[2]), "r"(a[3]), "r"(b[0]), "r"(b[1]));
}

// ---------------- init ----------------
__global__ void init_kernel() {
    int i = blockIdx.x * blockDim.x + threadIdx.x;
    if (i < NROWA) g_perm[i] = -1;
}

// ---------------- router: warp per token ----------------
__global__ __launch_bounds__(256) void router_kernel(
    const float* __restrict__ X, const float* __restrict__ Wr,
    const float* __restrict__ br)
{
    int gtid = blockIdx.x * blockDim.x + threadIdx.x;
    int t = gtid >> 5;
    int lane = gtid & 31;
    if (t >= T_TOK) return;

    const float* xr = X + (size_t)t * HDIM;
    float acc[NEXP];
#pragma unroll
    for (int e = 0; e < NEXP; e++) acc[e] = 0.0f;
    for (int i = lane; i < HDIM; i += 32) {
        float xv = xr[i];
#pragma unroll
        for (int e = 0; e < NEXP; e++) acc[e] += xv * Wr[e * HDIM + i];
    }
#pragma unroll
    for (int e = 0; e < NEXP; e++) {
#pragma unroll
        for (int o = 16; o > 0; o >>= 1)
            acc[e] += __shfl_down_sync(0xFFFFFFFFu, acc[e], o);
    }
    if (lane == 0) {
        float v[NEXP];
#pragma unroll
        for (int e = 0; e < NEXP; e++) v[e] = acc[e] + br[e];
        int i0 = 0; float v0 = v[0];
#pragma unroll
        for (int e = 1; e < NEXP; e++) if (v[e] > v0) { v0 = v[e]; i0 = e; }
        int i1 = (i0 == 0) ? 1 : 0; float v1 = v[i1];
#pragma unroll
        for (int e = 0; e < NEXP; e++)
            if (e != i0 && v[e] > v1) { v1 = v[e]; i1 = e; }
        float ex = expf(v1 - v0);
        float w0 = 1.0f / (1.0f + ex);
        g_idx[t * 2 + 0] = i0; g_idx[t * 2 + 1] = i1;
        g_wt [t * 2 + 0] = w0; g_wt [t * 2 + 1] = 1.0f - w0;
    }
}

// ---------------- rank phase A: per-chunk expert histogram ----------------
__global__ __launch_bounds__(CHKSZ) void cnt_kernel() {
    __shared__ int sc[NEXP];
    int tid = threadIdx.x;
    if (tid < NEXP) sc[tid] = 0;
    __syncthreads();
    int idx = g_idx[blockIdx.x * CHKSZ + tid];
    atomicAdd(&sc[idx & (NEXP - 1)], 1);
    __syncthreads();
    if (tid < NEXP) g_ccnt[blockIdx.x * NEXP + tid] = sc[tid];
}

// ---------------- rank phase B: per-expert chunk offsets (static base) ----
__global__ void off_kernel() {
    int e = threadIdx.x;        // <<<1, 8>>>
    if (e >= NEXP) return;
    int run = e * CAPE;
    for (int ch = 0; ch < NCHK; ch++) {
        g_coff[ch * NEXP + e] = run;
        run += g_ccnt[ch * NEXP + e];
    }
}

// ---------------- rank phase C: stable ballot scatter ----------------
__global__ __launch_bounds__(CHKSZ) void scat_kernel() {
    int wid = threadIdx.x >> 5, lane = threadIdx.x & 31;
    int e = wid;                 // warp w owns expert w (8 warps)
    int cur = g_coff[blockIdx.x * NEXP + e];
    unsigned lt = (1u << lane) - 1u;
#pragma unroll
    for (int gix = 0; gix < CHKSZ / 32; gix++) {
        int p = blockIdx.x * CHKSZ + gix * 32 + lane;
        int idx = g_idx[p];
        unsigned m = __ballot_sync(0xFFFFFFFFu, idx == e);
        if (idx == e) {
            int r = cur + __popc(m & lt);
            g_pos[p] = r;
            g_perm[r] = p >> 1;
        }
        cur += __popc(m);
    }
}

// ---------------- TF32 mma.sync GEMM, 3-stage cp.async pipeline ----------
// IS1=true : g_A1 = gelu(gather(X) @ W1[e]^T + b1[e]),  K=HDIM
// IS1=false: g_Y  =        g_A1   @ W2[e]^T + b2[e],    K=FDIM
template<int KDIM, int OUTDIM, bool IS1>
__global__ __launch_bounds__(256, 2) void moe_gemm_kernel(
    const float* __restrict__ Ain, const float* __restrict__ W,
    const float* __restrict__ bias)
{
    extern __shared__ char smem[];
    uint32_t sb = smem_u32(smem);
    int tid = threadIdx.x;
    int warp = tid >> 5, lane = tid & 31;
    int g = lane >> 2, t = lane & 3;
    int warp_m = warp & 1, warp_n = warp >> 1;     // 2 x 4 warp grid
    int row0 = blockIdx.y * 128, col0 = blockIdx.x * 128;

    int* stok = (int*)smem;
    int tk = -1;
    if (tid < 128) { tk = g_perm[row0 + tid]; stok[tid] = tk; }
    int havework = __syncthreads_or(tk >= 0);
    if (!havework) return;

    int e = row0 / CAPE;
    const float* We = W + (size_t)e * OUTDIM * KDIM;
    const float* Aptr = IS1 ? Ain : (const float*)g_A1;
    float* Out = IS1 ? (float*)g_A1 : (float*)g_Y;

    // per-thread load slots: 4 A rows + 4 B rows
    const float* aptr[4];
    const float* bptr[4];
    uint32_t soff[4];
#pragma unroll
    for (int i = 0; i < 4; i++) {
        int slot = i * 256 + tid;          // 0..1023
        int r = slot >> 3, k4 = slot & 7;
        soff[i] = (uint32_t)(r * (ASTRIDE * 4) + k4 * 16);
        if (IS1) {
            int tok = stok[r];
            if (tok < 0) tok = 0;          // pad rows: garbage, never read
            aptr[i] = Aptr + (size_t)tok * KDIM + k4 * 4;
        } else {
            aptr[i] = Aptr + (size_t)(row0 + r) * KDIM + k4 * 4;
        }
        bptr[i] = We + (size_t)(col0 + r) * KDIM + k4 * 4;
    }

    float acc[4][4][4];
#pragma unroll
    for (int mi = 0; mi < 4; mi++)
#pragma unroll
        for (int ni = 0; ni < 4; ni++)
#pragma unroll
            for (int q = 0; q < 4; q++) acc[mi][ni][q] = 0.0f;

    const int NCH = KDIM / KCH;
    uint32_t sbase = sb + SM_TILES;

    // prefetch stages 0,1
#pragma unroll
    for (int s = 0; s < 2; s++) {
        uint32_t sA = sbase + s * BUF_B;
        uint32_t sB = sA + TILE_B;
        int kb = s * KCH;
#pragma unroll
        for (int i = 0; i < 4; i++) {
            cp16(sA + soff[i], aptr[i] + kb);
            cp16(sB + soff[i], bptr[i] + kb);
        }
        asm volatile("cp.async.commit_group;" ::: "memory");
    }

#pragma unroll 1
    for (int c = 0; c < NCH; c++) {
        asm volatile("cp.async.wait_group 1;" ::: "memory");
        __syncthreads();

        // prefetch c+2 (overwrites buffer compute c-1 finished before sync)
        if (c + 2 < NCH) {
            uint32_t sA = sbase + ((c + 2) % NSTAGE) * BUF_B;
            uint32_t sB = sA + TILE_B;
            int kb = (c + 2) * KCH;
#pragma unroll
            for (int i = 0; i < 4; i++) {
                cp16(sA + soff[i], aptr[i] + kb);
                cp16(sB + soff[i], bptr[i] + kb);
            }
        }
        asm volatile("cp.async.commit_group;" ::: "memory");

        uint32_t sA = sbase + (c % NSTAGE) * BUF_B;
        uint32_t sB = sA + TILE_B;
#pragma unroll
        for (int ks = 0; ks < 4; ks++) {
            uint32_t a[4][4], b[4][2];
#pragma unroll
            for (int mi = 0; mi < 4; mi++) {
                uint32_t ad = sA + (uint32_t)((warp_m * 64 + mi * 16 + g) * (ASTRIDE * 4)
                                              + (ks * 8 + t) * 4);
                a[mi][0] = lds32(ad);
                a[mi][1] = lds32(ad + 8 * ASTRIDE * 4);
                a[mi][2] = lds32(ad + 16);
                a[mi][3] = lds32(ad + 8 * ASTRIDE * 4 + 16);
            }
#pragma unroll
            for (int ni = 0; ni < 4; ni++) {
                uint32_t bd = sB + (uint32_t)((warp_n * 32 + ni * 8 + g) * (ASTRIDE * 4)
                                              + (ks * 8 + t) * 4);
                b[ni][0] = lds32(bd);
                b[ni][1] = lds32(bd + 16);
            }
#pragma unroll
            for (int mi = 0; mi < 4; mi++)
#pragma unroll
                for (int ni = 0; ni < 4; ni++)
                    mma_tf32(acc[mi][ni], a[mi], b[ni]);
        }
    }

    // epilogue: bias (+ exact GELU for GEMM1)
    const float* be = bias + (size_t)e * OUTDIM;
#pragma unroll
    for (int mi = 0; mi < 4; mi++) {
        int r = row0 + warp_m * 64 + mi * 16 + g;
#pragma unroll
        for (int ni = 0; ni < 4; ni++) {
            int cc = col0 + warp_n * 32 + ni * 8 + 2 * t;
            float2 bv = *(const float2*)(be + cc);
            float v0 = acc[mi][ni][0] + bv.x;
            float v1 = acc[mi][ni][1] + bv.y;
            float v2 = acc[mi][ni][2] + bv.x;
            float v3 = acc[mi][ni][3] + bv.y;
            if (IS1) {
                v0 = 0.5f * v0 * (1.0f + erff(v0 * 0.70710678118654752f));
                v1 = 0.5f * v1 * (1.0f + erff(v1 * 0.70710678118654752f));
                v2 = 0.5f * v2 * (1.0f + erff(v2 * 0.70710678118654752f));
                v3 = 0.5f * v3 * (1.0f + erff(v3 * 0.70710678118654752f));
            }
            *(float2*)(Out + (size_t)r * OUTDIM + cc) = make_float2(v0, v1);
            *(float2*)(Out + (size_t)(r + 8) * OUTDIM + cc) = make_float2(v2, v3);
        }
    }
}

// ---------------- finalize: combine + residual + layernorm ----------------
__global__ __launch_bounds__(256) void finalize_kernel(
    const float* __restrict__ X, const float* __restrict__ ln_w,
    const float* __restrict__ ln_b, float* __restrict__ out)
{
    int t = blockIdx.x;
    int tid = threadIdx.x;

    float w0 = g_wt[t * 2 + 0], w1 = g_wt[t * 2 + 1];
    int q0 = g_pos[t * 2 + 0];
    int q1 = g_pos[t * 2 + 1];
    if ((unsigned)q0 >= NROW) q0 = 0;
    if ((unsigned)q1 >= NROW) q1 = 0;
    const float4* y0 = (const float4*)(g_Y + (size_t)q0 * HDIM);
    const float4* y1 = (const float4*)(g_Y + (size_t)q1 * HDIM);
    const float4* xv = (const float4*)(X + (size_t)t * HDIM);

    float4 a = xv[tid], c0 = y0[tid], c1 = y1[tid];
    float4 z;
    z.x = a.x + w0 * c0.x + w1 * c1.x;
    z.y = a.y + w0 * c0.y + w1 * c1.y;
    z.z = a.z + w0 * c0.z + w1 * c1.z;
    z.w = a.w + w0 * c0.w + w1 * c1.w;
    float s = z.x + z.y + z.z + z.w;
    float sq = z.x * z.x + z.y * z.y + z.z * z.z + z.w * z.w;

#pragma unroll
    for (int o = 16; o > 0; o >>= 1) {
        s  += __shfl_down_sync(0xFFFFFFFFu, s,  o);
        sq += __shfl_down_sync(0xFFFFFFFFu, sq, o);
    }
    __shared__ float rs[8], rq[8];
    int wid = tid >> 5, lane = tid & 31;
    if (lane == 0) { rs[wid] = s; rq[wid] = sq; }
    __syncthreads();
    if (tid == 0) {
        float aa = 0.0f, bb = 0.0f;
#pragma unroll
        for (int w = 0; w < 8; w++) { aa += rs[w]; bb += rq[w]; }
        rs[0] = aa; rq[0] = bb;
    }
    __syncthreads();
    float mu = rs[0] * (1.0f / HDIM);
    float var = rq[0] * (1.0f / HDIM) - mu * mu;
    float rstd = rsqrtf(var + 1e-12f);

    float4 gw = ((const float4*)ln_w)[tid];
    float4 gb = ((const float4*)ln_b)[tid];
    float4 o;
    o.x = (z.x - mu) * rstd * gw.x + gb.x;
    o.y = (z.y - mu) * rstd * gw.y + gb.y;
    o.z = (z.z - mu) * rstd * gw.z + gb.z;
    o.w = (z.w - mu) * rstd * gw.w + gb.w;
    ((float4*)(out + (size_t)t * HDIM))[tid] = o;
}

// ---------------- launch ----------------
extern "C" void kernel_launch(void* const* d_in, const int* in_sizes, int n_in,
                              void* d_out, int out_size) {
    const float *X = 0, *Wr = 0, *br = 0, *W1 = 0, *b1 = 0, *W2 = 0, *b2 = 0,
                *ln_w = 0, *ln_b = 0;
    for (int i = 0; i < n_in; i++) {
        const float* p = (const float*)d_in[i];
        switch (in_sizes[i]) {
            case T_TOK * HDIM:        if (!X) X = p; break;
            case NEXP * FDIM * HDIM:  if (!W1) W1 = p; else W2 = p; break;
            case NEXP * FDIM:         if (!b1) b1 = p; break;
            case NEXP * HDIM:         if (!Wr) Wr = p; else b2 = p; break;
            case NEXP:                if (!br) br = p; break;
            case HDIM:                if (!ln_w) ln_w = p; else ln_b = p; break;
            default: break;
        }
    }
    if (!X || !Wr || !br || !W1 || !b1 || !W2 || !b2 || !ln_w || !ln_b) {
        X = (const float*)d_in[0]; Wr = (const float*)d_in[1];
        br = (const float*)d_in[2]; W1 = (const float*)d_in[3];
        b1 = (const float*)d_in[4]; W2 = (const float*)d_in[5];
        b2 = (const float*)d_in[6]; ln_w = (const float*)d_in[7];
        ln_b = (const float*)d_in[8];
    }
    float* out = (float*)d_out;

    cudaFuncSetAttribute(moe_gemm_kernel<HDIM, FDIM, true>,
                         cudaFuncAttributeMaxDynamicSharedMemorySize, SM_TOTAL);
    cudaFuncSetAttribute(moe_gemm_kernel<FDIM, HDIM, false>,
                         cudaFuncAttributeMaxDynamicSharedMemorySize, SM_TOTAL);

    init_kernel<<<(NROWA + 255) / 256, 256>>>();
    router_kernel<<<(T_TOK * 32) / 256, 256>>>(X, Wr, br);
    cnt_kernel<<<NCHK, CHKSZ>>>();
    off_kernel<<<1, 8>>>();
    scat_kernel<<<NCHK, CHKSZ>>>();
    moe_gemm_kernel<HDIM, FDIM, true>
        <<<dim3(FDIM / 128, ROWTILES), 256, SM_TOTAL>>>(X, W1, b1);
    moe_gemm_kernel<FDIM, HDIM, false>
        <<<dim3(HDIM / 128, ROWTILES), 256, SM_TOTAL>>>(nullptr, W2, b2);
    finalize_kernel<<<T_TOK, 256>>>(X, ln_w, ln_b, out);
}